// round 3
// baseline (speedup 1.0000x reference)
#include <cuda_runtime.h>
#include <cuda_fp16.h>
#include <math.h>

#define NSTEP 256
#define W 256
#define Hh 256
#define Dd 256

// Packed grid: P[z][y][x] = 4 x fp16 corners:
//   .x : half2( sat g[z ][y][x], sat g[z ][y+1][x] )   -> (c000, c010)
//   .y : half2( sat g[z1][y][x], sat g[z1][y+1][x] )   -> (c100, c110)
// 256^3 * 8B = 128 MB static device scratch.
__device__ uint2 g_P[256 * 256 * 256];

// ---------------- Pre-pass: fp32 grid -> saturated 4-corner fp16 pack ----------------
__global__ void __launch_bounds__(64)
pack_kernel(const float* __restrict__ g)
{
    int z  = blockIdx.x;
    int y  = blockIdx.y;
    int x4 = threadIdx.x << 2;                 // 4 consecutive x voxels per thread
    int y1 = (y < 255) ? y + 1 : y;
    int z1 = (z < 255) ? z + 1 : z;

    const float4 r00 = *reinterpret_cast<const float4*>(g + (((z  << 8) + y ) << 8) + x4);
    const float4 r01 = *reinterpret_cast<const float4*>(g + (((z  << 8) + y1) << 8) + x4);
    const float4 r10 = *reinterpret_cast<const float4*>(g + (((z1 << 8) + y ) << 8) + x4);
    const float4 r11 = *reinterpret_cast<const float4*>(g + (((z1 << 8) + y1) << 8) + x4);

    uint2 o[4];
    {
        __half2 a, b;
        a = __floats2half2_rn(__saturatef(r00.x), __saturatef(r01.x));
        b = __floats2half2_rn(__saturatef(r10.x), __saturatef(r11.x));
        o[0].x = *reinterpret_cast<unsigned int*>(&a);
        o[0].y = *reinterpret_cast<unsigned int*>(&b);
        a = __floats2half2_rn(__saturatef(r00.y), __saturatef(r01.y));
        b = __floats2half2_rn(__saturatef(r10.y), __saturatef(r11.y));
        o[1].x = *reinterpret_cast<unsigned int*>(&a);
        o[1].y = *reinterpret_cast<unsigned int*>(&b);
        a = __floats2half2_rn(__saturatef(r00.z), __saturatef(r01.z));
        b = __floats2half2_rn(__saturatef(r10.z), __saturatef(r11.z));
        o[2].x = *reinterpret_cast<unsigned int*>(&a);
        o[2].y = *reinterpret_cast<unsigned int*>(&b);
        a = __floats2half2_rn(__saturatef(r00.w), __saturatef(r01.w));
        b = __floats2half2_rn(__saturatef(r10.w), __saturatef(r11.w));
        o[3].x = *reinterpret_cast<unsigned int*>(&a);
        o[3].y = *reinterpret_cast<unsigned int*>(&b);
    }

    uint2* dst = g_P + (((z << 8) + y) << 8) + x4;
    uint4 w0 = make_uint4(o[0].x, o[0].y, o[1].x, o[1].y);
    uint4 w1 = make_uint4(o[2].x, o[2].y, o[3].x, o[3].y);
    *reinterpret_cast<uint4*>(dst)     = w0;
    *reinterpret_cast<uint4*>(dst + 2) = w1;
}

// ---------------- Main kernel: warp per ray, lane = step index ----------------
__device__ __forceinline__ float safe_inv(float d) {
    const float EPSF = 1e-8f;
    float s = (d > 0.f) ? 1.f : ((d < 0.f) ? -1.f : 0.f);
    float w = (fabsf(d) < EPSF) ? fmaf(s, EPSF, EPSF) : d;
    return 1.0f / w;
}

__global__ void __launch_bounds__(256)
transmittance_kernel(const float* __restrict__ rays,
                     float* __restrict__ out,
                     int n_rays)
{
    const float EPSF = 1e-8f;
    int gwarp = (int)((blockIdx.x * 256u + threadIdx.x) >> 5);
    int lane  = threadIdx.x & 31;
    if (gwarp >= n_rays) return;

    const float* r = rays + (size_t)gwarp * 6;
    float ox = __ldg(r + 0), oy = __ldg(r + 1), oz = __ldg(r + 2);
    float dx = __ldg(r + 3), dy = __ldg(r + 4), dz = __ldg(r + 5);

    float nrm = sqrtf(fmaf(dx, dx, fmaf(dy, dy, dz * dz))) + EPSF;
    float inv_n = 1.0f / nrm;
    dx *= inv_n; dy *= inv_n; dz *= inv_n;

    float ix = safe_inv(dx), iy = safe_inv(dy), iz = safe_inv(dz);
    float tax = (-1.f - ox) * ix, tbx = (1.f - ox) * ix;
    float tay = (-1.f - oy) * iy, tby = (1.f - oy) * iy;
    float taz = (-1.f - oz) * iz, tbz = (1.f - oz) * iz;

    float tmin = fmaxf(fmaxf(fminf(tax, tbx), fminf(tay, tby)), fminf(taz, tbz));
    float tmax = fminf(fminf(fmaxf(tax, tbx), fmaxf(tay, tby)), fmaxf(taz, tbz));
    tmin = fmaxf(tmin, 0.0f);

    bool valid = (tmax > tmin);
    if (!valid) {                       // uniform across the warp
        if (lane == 0) out[gwarp] = 1.0f;
        return;
    }
    float seg = tmax - tmin;

    const uint2* __restrict__ P = g_P;
    float sum = 0.0f;

    #pragma unroll 4
    for (int it = 0; it < NSTEP / 32; ++it) {
        int i = it * 32 + lane;          // 32 consecutive steps per warp-instruction
        float frac = ((float)i + 0.5f) * (1.0f / (float)NSTEP);
        float t = fmaf(seg, frac, tmin);

        float gx = (fmaf(t, dx, ox) + 1.0f) * (0.5f * (W  - 1));
        float gy = (fmaf(t, dy, oy) + 1.0f) * (0.5f * (Hh - 1));
        float gz = (fmaf(t, dz, oz) + 1.0f) * (0.5f * (Dd - 1));

        float x0f = fminf(fmaxf(floorf(gx), 0.f), (float)(W  - 2));
        float y0f = fminf(fmaxf(floorf(gy), 0.f), (float)(Hh - 2));
        float z0f = fminf(fmaxf(floorf(gz), 0.f), (float)(Dd - 2));
        float fx = __saturatef(gx - x0f);
        float fy = __saturatef(gy - y0f);
        float fz = __saturatef(gz - z0f);
        int x0 = (int)x0f, y0 = (int)y0f, z0 = (int)z0f;

        int base = (z0 << 16) + (y0 << 8) + x0;

        // 2 loads fetch all 8 corners (y,z pairs packed per voxel)
        uint2 v0 = __ldg(P + base);      // (c000,c010),(c100,c110)
        uint2 v1 = __ldg(P + base + 1);  // (c001,c011),(c101,c111)

        float2 A = __half22float2(*reinterpret_cast<__half2*>(&v0.x)); // c000,c010
        float2 C = __half22float2(*reinterpret_cast<__half2*>(&v0.y)); // c100,c110
        float2 B = __half22float2(*reinterpret_cast<__half2*>(&v1.x)); // c001,c011
        float2 D = __half22float2(*reinterpret_cast<__half2*>(&v1.y)); // c101,c111

        float c00 = fmaf(B.x - A.x, fx, A.x);
        float c01 = fmaf(B.y - A.y, fx, A.y);
        float c10 = fmaf(D.x - C.x, fx, C.x);
        float c11 = fmaf(D.y - C.y, fx, C.y);
        float c0  = fmaf(c01 - c00, fy, c00);
        float c1  = fmaf(c11 - c10, fy, c10);
        sum += fmaf(c1 - c0, fz, c0);
    }

    #pragma unroll
    for (int o = 16; o; o >>= 1)
        sum += __shfl_xor_sync(0xffffffffu, sum, o);

    if (lane == 0) {
        float dt = seg * (1.0f / (float)NSTEP);
        float tau = 10.0f * sum * dt;
        out[gwarp] = expf(-tau);
    }
}

extern "C" void kernel_launch(void* const* d_in, const int* in_sizes, int n_in,
                              void* d_out, int out_size)
{
    const float* rays = (const float*)d_in[0];
    const float* grid = (const float*)d_in[1];
    float* out = (float*)d_out;
    int n_rays = in_sizes[0] / 6;

    // Pre-pass: one block per (z,y) row, 64 threads x 4 voxels
    dim3 pgrid(256, 256);
    pack_kernel<<<pgrid, 64>>>(grid);

    // Main: one warp per ray
    int total_threads = n_rays * 32;
    transmittance_kernel<<<(total_threads + 255) / 256, 256>>>(rays, out, n_rays);
}

// round 4
// speedup vs baseline: 1.3385x; 1.3385x over previous
#include <cuda_runtime.h>
#include <cuda_fp16.h>
#include <math.h>

#define NSTEP 256
#define W 256
#define Hh 256
#define Dd 256

// Packed grid (64 MB, L2-resident): g_Y[(z<<16)+(y<<8)+x] = half2( sat g[z][y][x], sat g[z][y+1][x] )
__device__ __half2 g_Y[256 * 256 * 256];

// ---------------- Pre-pass: fp32 grid -> saturated half2 y-pair layout ----------------
__global__ void __launch_bounds__(256)
pack_kernel(const float* __restrict__ g)
{
    int idx = blockIdx.x * 256 + threadIdx.x;
    int lin = idx << 2;                            // linear voxel index (x fastest)
    int y = (lin >> 8) & 255;
    int zy1 = (y < 255) ? (lin + 256) : lin;       // row y+1 (clamped), same z,x

    float4 r0 = *reinterpret_cast<const float4*>(g + lin);
    float4 r1 = *reinterpret_cast<const float4*>(g + zy1);

    __half2 h0 = __floats2half2_rn(__saturatef(r0.x), __saturatef(r1.x));
    __half2 h1 = __floats2half2_rn(__saturatef(r0.y), __saturatef(r1.y));
    __half2 h2 = __floats2half2_rn(__saturatef(r0.z), __saturatef(r1.z));
    __half2 h3 = __floats2half2_rn(__saturatef(r0.w), __saturatef(r1.w));

    uint4 pack;
    pack.x = *reinterpret_cast<unsigned int*>(&h0);
    pack.y = *reinterpret_cast<unsigned int*>(&h1);
    pack.z = *reinterpret_cast<unsigned int*>(&h2);
    pack.w = *reinterpret_cast<unsigned int*>(&h3);
    *reinterpret_cast<uint4*>(g_Y + lin) = pack;
}

// ---------------- Main kernel: warp per ray, lane = step index ----------------
__device__ __forceinline__ float safe_inv(float d) {
    const float EPSF = 1e-8f;
    float s = (d > 0.f) ? 1.f : ((d < 0.f) ? -1.f : 0.f);
    float w = (fabsf(d) < EPSF) ? fmaf(s, EPSF, EPSF) : d;
    return 1.0f / w;
}

__global__ void __launch_bounds__(256)
transmittance_kernel(const float* __restrict__ rays,
                     float* __restrict__ out,
                     int n_rays)
{
    const float EPSF = 1e-8f;
    int gwarp = (int)((blockIdx.x * 256u + threadIdx.x) >> 5);
    int lane  = threadIdx.x & 31;
    if (gwarp >= n_rays) return;

    const float* r = rays + (size_t)gwarp * 6;
    float ox = __ldg(r + 0), oy = __ldg(r + 1), oz = __ldg(r + 2);
    float dx = __ldg(r + 3), dy = __ldg(r + 4), dz = __ldg(r + 5);

    float nrm = sqrtf(fmaf(dx, dx, fmaf(dy, dy, dz * dz))) + EPSF;
    float inv_n = 1.0f / nrm;
    dx *= inv_n; dy *= inv_n; dz *= inv_n;

    float ixr = safe_inv(dx), iyr = safe_inv(dy), izr = safe_inv(dz);
    float tax = (-1.f - ox) * ixr, tbx = (1.f - ox) * ixr;
    float tay = (-1.f - oy) * iyr, tby = (1.f - oy) * iyr;
    float taz = (-1.f - oz) * izr, tbz = (1.f - oz) * izr;

    float tmin = fmaxf(fmaxf(fminf(tax, tbx), fminf(tay, tby)), fminf(taz, tbz));
    float tmax = fminf(fminf(fmaxf(tax, tbx), fmaxf(tay, tby)), fmaxf(taz, tbz));
    tmin = fmaxf(tmin, 0.0f);

    bool valid = (tmax > tmin);
    if (!valid) {                        // uniform across the warp
        if (lane == 0) out[gwarp] = 1.0f;
        return;
    }
    float seg = tmax - tmin;

    const uint4* __restrict__ U4 = reinterpret_cast<const uint4*>(g_Y);
    float sum = 0.0f;

    #pragma unroll 2
    for (int it = 0; it < NSTEP / 32; ++it) {
        int i = it * 32 + lane;          // 32 consecutive steps per warp-instruction
        float frac = ((float)i + 0.5f) * (1.0f / (float)NSTEP);
        float t = fmaf(seg, frac, tmin);

        float gx = (fmaf(t, dx, ox) + 1.0f) * (0.5f * (W  - 1));
        float gy = (fmaf(t, dy, oy) + 1.0f) * (0.5f * (Hh - 1));
        float gz = (fmaf(t, dz, oz) + 1.0f) * (0.5f * (Dd - 1));

        float x0f = fminf(fmaxf(floorf(gx), 0.f), (float)(W  - 2));
        float y0f = fminf(fmaxf(floorf(gy), 0.f), (float)(Hh - 2));
        float z0f = fminf(fmaxf(floorf(gz), 0.f), (float)(Dd - 2));
        float fx = __saturatef(gx - x0f);
        float fy = __saturatef(gy - y0f);
        float fz = __saturatef(gz - z0f);
        int x0 = (int)x0f, y0 = (int)y0f, z0 = (int)z0f;

        int k = x0 >> 2;                 // uint4 index within row
        int j = x0 & 3;                  // word within uint4
        int row0 = (z0 << 14) + (y0 << 6) + k;     // z0 plane
        int row1 = row0 + (1 << 14);               // z0+1 plane

        // One 16B load per z-plane covers both x corners for 75% of lanes
        uint4 v0 = __ldg(U4 + row0);
        uint4 v1 = __ldg(U4 + row1);
        unsigned e0 = 0, e1 = 0;
        if (j == 3) {                    // ~25% of lanes: x-pair straddles uint4
            e0 = __ldg(reinterpret_cast<const unsigned*>(U4 + row0 + 1));
            e1 = __ldg(reinterpret_cast<const unsigned*>(U4 + row1 + 1));
        }

        unsigned a0 = j==0 ? v0.x : j==1 ? v0.y : j==2 ? v0.z : v0.w;  // (c000,c010)
        unsigned b0 = j==0 ? v0.y : j==1 ? v0.z : j==2 ? v0.w : e0;    // (c001,c011)
        unsigned a1 = j==0 ? v1.x : j==1 ? v1.y : j==2 ? v1.z : v1.w;  // (c100,c110)
        unsigned b1 = j==0 ? v1.y : j==1 ? v1.z : j==2 ? v1.w : e1;    // (c101,c111)

        float2 A = __half22float2(*reinterpret_cast<__half2*>(&a0));
        float2 B = __half22float2(*reinterpret_cast<__half2*>(&b0));
        float2 C = __half22float2(*reinterpret_cast<__half2*>(&a1));
        float2 D = __half22float2(*reinterpret_cast<__half2*>(&b1));

        float c00 = fmaf(B.x - A.x, fx, A.x);
        float c01 = fmaf(B.y - A.y, fx, A.y);
        float c10 = fmaf(D.x - C.x, fx, C.x);
        float c11 = fmaf(D.y - C.y, fx, C.y);
        float c0  = fmaf(c01 - c00, fy, c00);
        float c1  = fmaf(c11 - c10, fy, c10);
        sum += fmaf(c1 - c0, fz, c0);
    }

    #pragma unroll
    for (int o = 16; o; o >>= 1)
        sum += __shfl_xor_sync(0xffffffffu, sum, o);

    if (lane == 0) {
        float dt = seg * (1.0f / (float)NSTEP);
        float tau = 10.0f * sum * dt;
        out[gwarp] = expf(-tau);
    }
}

extern "C" void kernel_launch(void* const* d_in, const int* in_sizes, int n_in,
                              void* d_out, int out_size)
{
    const float* rays = (const float*)d_in[0];
    const float* grid = (const float*)d_in[1];
    float* out = (float*)d_out;
    int n_rays = in_sizes[0] / 6;

    // Pre-pass: 256^3 voxels, 4 per thread
    int pack_threads = (256 * 256 * 256) / 4;
    pack_kernel<<<pack_threads / 256, 256>>>(grid);

    // Main: one warp per ray
    int total_threads = n_rays * 32;
    transmittance_kernel<<<(total_threads + 255) / 256, 256>>>(rays, out, n_rays);
}